// round 2
// baseline (speedup 1.0000x reference)
#include <cuda_runtime.h>

#define NN    10000
#define NE    320000
#define HID   16
#define NL    7
#define KTOT  10000

// gemm1 tiling
#define KC      576          // k per chunk (multiple of 32)
#define KSTEPS  (KC / 32)    // 18 inner steps
#define NCHUNK  18           // ceil(10000/576)
#define RPB     32           // rows per block (256 thr / 8 per row)

// -------- scratch (no allocations allowed) --------
__device__ float g_deg_out[NN];
__device__ float g_deg_in[NN];
__device__ float g_norm_src[NN];
__device__ float g_norm_dst[NN];
__device__ float g_h[NN * HID];    // layer1 (features@W1)*norm_src
__device__ float g_agg1[NN * HID];
__device__ float g_h2[NN * 8];     // layer2 pre-scatter, padded to 8
__device__ float g_agg2[NN * 8];
__device__ int   g_is64;

__device__ __forceinline__ int edge_at(const int* __restrict__ p, int e, int is64) {
    return is64 ? p[2 * e] : p[e];
}

// -------- zero all accumulators --------
__global__ void zero_kernel() {
    int i = blockIdx.x * blockDim.x + threadIdx.x;
    if (i < NN) { g_deg_out[i] = 0.f; g_deg_in[i] = 0.f; }
    if (i < NN * HID) { g_h[i] = 0.f; g_agg1[i] = 0.f; }
    if (i < NN * 8) g_agg2[i] = 0.f;
}

// -------- detect int64 vs int32 edge indices --------
__global__ void detect_kernel(const int* __restrict__ src, const int* __restrict__ dst) {
    int t = threadIdx.x;  // 256 threads
    int v = src[2 * t + 1] | dst[2 * t + 1];
    int any = __syncthreads_or(v != 0);
    if (t == 0) g_is64 = any ? 0 : 1;  // all odd words zero -> int64
}

// -------- degrees --------
__global__ void degree_kernel(const int* __restrict__ src, const int* __restrict__ dst) {
    int e = blockIdx.x * blockDim.x + threadIdx.x;
    if (e >= NE) return;
    int is64 = g_is64;
    atomicAdd(&g_deg_out[edge_at(src, e, is64)], 1.f);
    atomicAdd(&g_deg_in[edge_at(dst, e, is64)], 1.f);
}

// -------- rsqrt norms --------
__global__ void norm_kernel() {
    int i = blockIdx.x * blockDim.x + threadIdx.x;
    if (i >= NN) return;
    g_norm_src[i] = rsqrtf(fmaxf(g_deg_out[i], 1.f));
    g_norm_dst[i] = rsqrtf(fmaxf(g_deg_in[i], 1.f));
}

// -------- layer1 GEMM (coalesced): 8 threads per row, f32x2 FMAs.
// grid = (ceil(NN/32), NCHUNK), block = 256.
// W chunk staged in smem as 16B units, stride 5 units per k, XOR-swizzled.
__global__ __launch_bounds__(256, 3) void gemm1_kernel(const float* __restrict__ A,
                                                       const float* __restrict__ W1) {
    __shared__ ulonglong2 ws2[KC * 5];   // 46080 B

    const int t = threadIdx.x;
    const int k0 = blockIdx.y * KC;

    // ---- stage W chunk: logical (kl, u) -> phys kl*5 + (u ^ ((kl>>2)&3))
    for (int i = t; i < KC * 4; i += 256) {
        int kl = i >> 2, u = i & 3;
        int k = k0 + kl;
        ulonglong2 v;
        if (k < KTOT) {
            v = *reinterpret_cast<const ulonglong2*>(W1 + (size_t)k * HID + u * 4);
        } else {
            v.x = 0ull; v.y = 0ull;
        }
        ws2[kl * 5 + (u ^ ((kl >> 2) & 3))] = v;
    }
    __syncthreads();

    const int lane8 = t & 7;            // slot within row
    const int r = blockIdx.x * RPB + (t >> 3);
    const bool rok = r < NN;
    const int swz = t & 3;              // == ((kl>>2)&3) for this thread's k values
    const float* ap = A + (size_t)r * KTOT + k0 + lane8 * 4;

    unsigned long long acc[8];
#pragma unroll
    for (int j = 0; j < 8; j++) acc[j] = 0ull;

#pragma unroll 2
    for (int ks = 0; ks < KSTEPS; ks++) {
        int k = k0 + ks * 32 + lane8 * 4;
        float4 a = make_float4(0.f, 0.f, 0.f, 0.f);
        if (rok && k < KTOT) a = *reinterpret_cast<const float4*>(ap + ks * 32);
        int klb = ks * 32 + lane8 * 4;
#pragma unroll
        for (int kk = 0; kk < 4; kk++) {
            float av = kk == 0 ? a.x : kk == 1 ? a.y : kk == 2 ? a.z : a.w;
            unsigned long long d;
            asm("mov.b64 %0, {%1, %1};" : "=l"(d) : "r"(__float_as_uint(av)));
            int base = (klb + kk) * 5;
#pragma unroll
            for (int u = 0; u < 4; u++) {
                ulonglong2 w = ws2[base + (u ^ swz)];
                asm("fma.rn.f32x2 %0, %1, %2, %0;" : "+l"(acc[2 * u])     : "l"(d), "l"(w.x));
                asm("fma.rn.f32x2 %0, %1, %2, %0;" : "+l"(acc[2 * u + 1]) : "l"(d), "l"(w.y));
            }
        }
    }

    // ---- butterfly reduce across the 8 lanes of each row group
#pragma unroll
    for (int j = 0; j < 8; j++) {
        double v = __longlong_as_double((long long)acc[j]);
#pragma unroll
        for (int m = 4; m >= 1; m >>= 1) {
            double o = __shfl_xor_sync(0xffffffffu, v, m, 8);
            unsigned long long x = (unsigned long long)__double_as_longlong(v);
            unsigned long long y = (unsigned long long)__double_as_longlong(o);
            asm("add.rn.f32x2 %0, %0, %1;" : "+l"(x) : "l"(y));
            v = __longlong_as_double((long long)x);
        }
        acc[j] = (unsigned long long)__double_as_longlong(v);
    }

    if (rok) {
        float ns = g_norm_src[r];
        float2 p = *reinterpret_cast<float2*>(&acc[lane8]);  // lane handles col-pair lane8
        atomicAdd(&g_h[r * HID + 2 * lane8],     p.x * ns);
        atomicAdd(&g_h[r * HID + 2 * lane8 + 1], p.y * ns);
    }
}

// -------- edge scatter 1: agg1[dst] += h[src] --------
__global__ void scatter1_kernel(const int* __restrict__ src, const int* __restrict__ dst) {
    int idx = blockIdx.x * blockDim.x + threadIdx.x;
    if (idx >= NE * HID) return;
    int e = idx >> 4, j = idx & 15;
    int is64 = g_is64;
    int s = edge_at(src, e, is64);
    int d = edge_at(dst, e, is64);
    atomicAdd(&g_agg1[d * HID + j], g_h[s * HID + j]);
}

// -------- relu + norm + layer2 GEMM (16x7) --------
__global__ void act_gemm2_kernel(const float* __restrict__ b1, const float* __restrict__ W2) {
    __shared__ float W2s[HID * NL];
    __shared__ float b1s[HID];
    int t = threadIdx.x;
    if (t < HID * NL) W2s[t] = W2[t];
    if (t < HID) b1s[t] = b1[t];
    __syncthreads();
    int i = blockIdx.x * blockDim.x + t;
    if (i >= NN) return;
    float nd = g_norm_dst[i], ns = g_norm_src[i];
    float o[NL];
#pragma unroll
    for (int l = 0; l < NL; l++) o[l] = 0.f;
    const float4* ag = (const float4*)(g_agg1 + i * HID);
#pragma unroll
    for (int q = 0; q < 4; q++) {
        float4 v = ag[q];
        float hv[4] = {v.x, v.y, v.z, v.w};
#pragma unroll
        for (int u = 0; u < 4; u++) {
            int j = q * 4 + u;
            float h1 = fmaxf(hv[u] * nd + b1s[j], 0.f) * ns;
#pragma unroll
            for (int l = 0; l < NL; l++) o[l] += h1 * W2s[j * NL + l];
        }
    }
#pragma unroll
    for (int l = 0; l < NL; l++) g_h2[i * 8 + l] = o[l];
}

// -------- edge scatter 2: agg2[dst] += h2[src] --------
__global__ void scatter2_kernel(const int* __restrict__ src, const int* __restrict__ dst) {
    int idx = blockIdx.x * blockDim.x + threadIdx.x;
    if (idx >= NE * 8) return;
    int e = idx >> 3, j = idx & 7;
    if (j >= NL) return;
    int is64 = g_is64;
    int s = edge_at(src, e, is64);
    int d = edge_at(dst, e, is64);
    atomicAdd(&g_agg2[d * 8 + j], g_h2[s * 8 + j]);
}

// -------- epilogue: out = agg2 * norm_dst + b2 --------
__global__ void final_kernel(const float* __restrict__ b2, float* __restrict__ out) {
    int idx = blockIdx.x * blockDim.x + threadIdx.x;
    if (idx >= NN * NL) return;
    int i = idx / NL, l = idx - i * NL;
    out[idx] = g_agg2[i * 8 + l] * g_norm_dst[i] + __ldg(&b2[l]);
}

extern "C" void kernel_launch(void* const* d_in, const int* in_sizes, int n_in,
                              void* d_out, int out_size) {
    const float* features = (const float*)d_in[0];
    const int*   src      = (const int*)d_in[1];   // int32 or int64 (detected)
    const int*   dst      = (const int*)d_in[2];
    const float* W1       = (const float*)d_in[3];
    const float* b1       = (const float*)d_in[4];
    const float* W2       = (const float*)d_in[5];
    const float* b2       = (const float*)d_in[6];
    float* out = (float*)d_out;

    zero_kernel<<<(NN * HID + 255) / 256, 256>>>();
    detect_kernel<<<1, 256>>>(src, dst);
    degree_kernel<<<(NE + 255) / 256, 256>>>(src, dst);
    norm_kernel<<<(NN + 255) / 256, 256>>>();
    gemm1_kernel<<<dim3((NN + RPB - 1) / RPB, NCHUNK), 256>>>(features, W1);
    scatter1_kernel<<<(NE * HID + 255) / 256, 256>>>(src, dst);
    act_gemm2_kernel<<<(NN + 255) / 256, 256>>>(b1, W2);
    scatter2_kernel<<<(NE * 8 + 255) / 256, 256>>>(src, dst);
    final_kernel<<<(NN * NL + 255) / 256, 256>>>(b2, out);
}

// round 3
// speedup vs baseline: 2.1223x; 2.1223x over previous
#include <cuda_runtime.h>

#define NN    10000
#define NE    320000
#define HID   16
#define NL    7
#define KTOT  10000

// gemm1 tiling
#define KS      32            // k per inner step
#define KC      960           // k per chunk (30 steps)
#define NSPLIT  11            // ceil(10000/960)
#define RPB     256           // rows per block
#define TPB     128           // threads (2 rows/thread)

// -------- scratch (no allocations allowed) --------
__device__ float g_deg_out[NN];
__device__ float g_deg_in[NN];
__device__ float g_norm_src[NN];
__device__ float g_norm_dst[NN];
__device__ float g_h[NN * HID];
__device__ float g_agg1[NN * HID];
__device__ float g_h2[NN * 8];
__device__ float g_agg2[NN * 8];
__device__ int   g_is64;

// -------- zero accumulators --------
__global__ void zero_kernel() {
    int i = blockIdx.x * blockDim.x + threadIdx.x;
    if (i < NN) { g_deg_out[i] = 0.f; g_deg_in[i] = 0.f; }
    if (i < NN * HID) { g_h[i] = 0.f; g_agg1[i] = 0.f; }
}

// -------- degrees (+ inline int64/int32 detection, published for later kernels) --------
__global__ void degree_kernel(const int* __restrict__ src, const int* __restrict__ dst) {
    // int64 node ids < 2^31 -> all odd 32-bit words zero; int32: random ids, never all zero
    int is64 = ((src[1] | src[3] | src[5] | src[7] |
                 dst[1] | dst[3] | dst[5] | dst[7]) == 0) ? 1 : 0;
    int e = blockIdx.x * blockDim.x + threadIdx.x;
    if (e == 0) g_is64 = is64;
    if (e >= NE) return;
    int s = is64 ? src[2 * e] : src[e];
    int d = is64 ? dst[2 * e] : dst[e];
    atomicAdd(&g_deg_out[s], 1.f);
    atomicAdd(&g_deg_in[d], 1.f);
}

// -------- rsqrt norms --------
__global__ void norm_kernel() {
    int i = blockIdx.x * blockDim.x + threadIdx.x;
    if (i >= NN) return;
    g_norm_src[i] = rsqrtf(fmaxf(g_deg_out[i], 1.f));
    g_norm_dst[i] = rsqrtf(fmaxf(g_deg_in[i], 1.f));
}

// -------- layer1 GEMM: coalesced LDG staging + broadcast-W compute --------
__global__ __launch_bounds__(TPB, 5) void gemm1_kernel(const float* __restrict__ A,
                                                       const float* __restrict__ W1) {
    __shared__ float As[RPB][KS + 4];   // pitch 36 floats (odd 16B-unit stride) = 36864 B
    __shared__ float Wsub[KS][HID];     // 2048 B

    const int t  = threadIdx.x;
    const int r0 = blockIdx.x * RPB;
    const int k0 = blockIdx.y * KC;
    const int ksteps = min(KC / KS, (KTOT - k0 + KS - 1) / KS);

    const int rA = r0 + t;
    const int rB = r0 + t + TPB;

    unsigned long long acc0[8], acc1[8];
#pragma unroll
    for (int j = 0; j < 8; j++) { acc0[j] = 0ull; acc1[j] = 0ull; }

    for (int s = 0; s < ksteps; s++) {
        const int kbase = k0 + s * KS;
        __syncthreads();
        // stage A tile: 256 rows x 32 k = 2048 float4, 16 per thread.
        // warp-LDG covers 4 rows x 128B aligned lines -> 4 wavefronts (optimal).
#pragma unroll
        for (int p = 0; p < 16; p++) {
            int i = t + TPB * p;
            int row = i >> 3, u = i & 7;
            int gr = r0 + row;
            int gk = kbase + u * 4;
            float4 v = make_float4(0.f, 0.f, 0.f, 0.f);
            if (gr < NN && gk < KTOT)
                v = *reinterpret_cast<const float4*>(A + (size_t)gr * KTOT + gk);
            *reinterpret_cast<float4*>(&As[row][u * 4]) = v;
        }
        // stage W tile: 32 x 16 = 128 float4, 1 per thread
        {
            int kw = t >> 2, u = t & 3;
            int gk = kbase + kw;
            float4 v = make_float4(0.f, 0.f, 0.f, 0.f);
            if (gk < KTOT)
                v = *reinterpret_cast<const float4*>(W1 + (size_t)gk * HID + u * 4);
            *reinterpret_cast<float4*>(&Wsub[kw][u * 4]) = v;
        }
        __syncthreads();
        // compute: uniform k across warp -> W loads broadcast
#pragma unroll
        for (int kq = 0; kq < KS / 4; kq++) {
            float4 aA = *reinterpret_cast<const float4*>(&As[t][kq * 4]);
            float4 aB = *reinterpret_cast<const float4*>(&As[t + TPB][kq * 4]);
#pragma unroll
            for (int kk = 0; kk < 4; kk++) {
                float avA = kk == 0 ? aA.x : kk == 1 ? aA.y : kk == 2 ? aA.z : aA.w;
                float avB = kk == 0 ? aB.x : kk == 1 ? aB.y : kk == 2 ? aB.z : aB.w;
                unsigned long long dA, dB;
                asm("mov.b64 %0, {%1, %1};" : "=l"(dA) : "r"(__float_as_uint(avA)));
                asm("mov.b64 %0, {%1, %1};" : "=l"(dB) : "r"(__float_as_uint(avB)));
                const ulonglong2* wr = reinterpret_cast<const ulonglong2*>(Wsub[kq * 4 + kk]);
                ulonglong2 wa = wr[0], wb = wr[1], wc = wr[2], wd = wr[3];
                unsigned long long w[8] = {wa.x, wa.y, wb.x, wb.y, wc.x, wc.y, wd.x, wd.y};
#pragma unroll
                for (int j = 0; j < 8; j++) {
                    asm("fma.rn.f32x2 %0, %1, %2, %0;" : "+l"(acc0[j]) : "l"(dA), "l"(w[j]));
                    asm("fma.rn.f32x2 %0, %1, %2, %0;" : "+l"(acc1[j]) : "l"(dB), "l"(w[j]));
                }
            }
        }
    }

    if (rA < NN) {
        float ns = g_norm_src[rA];
#pragma unroll
        for (int j = 0; j < 8; j++) {
            float2 p = *reinterpret_cast<float2*>(&acc0[j]);
            atomicAdd(&g_h[rA * HID + 2 * j],     p.x * ns);
            atomicAdd(&g_h[rA * HID + 2 * j + 1], p.y * ns);
        }
    }
    if (rB < NN) {
        float ns = g_norm_src[rB];
#pragma unroll
        for (int j = 0; j < 8; j++) {
            float2 p = *reinterpret_cast<float2*>(&acc1[j]);
            atomicAdd(&g_h[rB * HID + 2 * j],     p.x * ns);
            atomicAdd(&g_h[rB * HID + 2 * j + 1], p.y * ns);
        }
    }
}

// -------- edge scatter 1 (float4-vectorized): agg1[dst] += h[src] --------
__global__ void scatter1_kernel(const int* __restrict__ src, const int* __restrict__ dst) {
    int idx = blockIdx.x * blockDim.x + threadIdx.x;
    if (idx >= NE * 4) return;
    int e = idx >> 2, q = idx & 3;
    int is64 = g_is64;
    int s = is64 ? src[2 * e] : src[e];
    int d = is64 ? dst[2 * e] : dst[e];
    float4 v = *reinterpret_cast<const float4*>(&g_h[s * HID + q * 4]);
    float* o = &g_agg1[d * HID + q * 4];
    atomicAdd(o + 0, v.x); atomicAdd(o + 1, v.y);
    atomicAdd(o + 2, v.z); atomicAdd(o + 3, v.w);
}

// -------- relu + norm + layer2 GEMM (16x7), also zeroes agg2 --------
__global__ void act_gemm2_kernel(const float* __restrict__ b1, const float* __restrict__ W2) {
    __shared__ float W2s[HID * NL];
    __shared__ float b1s[HID];
    int t = threadIdx.x;
    if (t < HID * NL) W2s[t] = W2[t];
    if (t < HID) b1s[t] = b1[t];
    __syncthreads();
    int i = blockIdx.x * blockDim.x + t;
    if (i >= NN) return;
    // zero agg2 row (scatter2 runs after this kernel)
    *reinterpret_cast<float4*>(&g_agg2[i * 8])     = make_float4(0.f, 0.f, 0.f, 0.f);
    *reinterpret_cast<float4*>(&g_agg2[i * 8 + 4]) = make_float4(0.f, 0.f, 0.f, 0.f);

    float nd = g_norm_dst[i], ns = g_norm_src[i];
    float o[8];
#pragma unroll
    for (int l = 0; l < 8; l++) o[l] = 0.f;
    const float4* ag = (const float4*)(g_agg1 + i * HID);
#pragma unroll
    for (int q = 0; q < 4; q++) {
        float4 v = ag[q];
        float hv[4] = {v.x, v.y, v.z, v.w};
#pragma unroll
        for (int u = 0; u < 4; u++) {
            int j = q * 4 + u;
            float h1 = fmaxf(hv[u] * nd + b1s[j], 0.f) * ns;
#pragma unroll
            for (int l = 0; l < NL; l++) o[l] += h1 * W2s[j * NL + l];
        }
    }
    *reinterpret_cast<float4*>(&g_h2[i * 8])     = make_float4(o[0], o[1], o[2], o[3]);
    *reinterpret_cast<float4*>(&g_h2[i * 8 + 4]) = make_float4(o[4], o[5], o[6], 0.f);
}

// -------- edge scatter 2 (float4-vectorized, padded to 8 cols) --------
__global__ void scatter2_kernel(const int* __restrict__ src, const int* __restrict__ dst) {
    int idx = blockIdx.x * blockDim.x + threadIdx.x;
    if (idx >= NE * 2) return;
    int e = idx >> 1, q = idx & 1;
    int is64 = g_is64;
    int s = is64 ? src[2 * e] : src[e];
    int d = is64 ? dst[2 * e] : dst[e];
    float4 v = *reinterpret_cast<const float4*>(&g_h2[s * 8 + q * 4]);
    float* o = &g_agg2[d * 8 + q * 4];
    atomicAdd(o + 0, v.x); atomicAdd(o + 1, v.y);
    atomicAdd(o + 2, v.z); atomicAdd(o + 3, v.w);
}

// -------- epilogue: out = agg2 * norm_dst + b2 --------
__global__ void final_kernel(const float* __restrict__ b2, float* __restrict__ out) {
    int idx = blockIdx.x * blockDim.x + threadIdx.x;
    if (idx >= NN * NL) return;
    int i = idx / NL, l = idx - i * NL;
    out[idx] = g_agg2[i * 8 + l] * g_norm_dst[i] + __ldg(&b2[l]);
}

extern "C" void kernel_launch(void* const* d_in, const int* in_sizes, int n_in,
                              void* d_out, int out_size) {
    const float* features = (const float*)d_in[0];
    const int*   src      = (const int*)d_in[1];   // int32 or int64 (runtime-detected)
    const int*   dst      = (const int*)d_in[2];
    const float* W1       = (const float*)d_in[3];
    const float* b1       = (const float*)d_in[4];
    const float* W2       = (const float*)d_in[5];
    const float* b2       = (const float*)d_in[6];
    float* out = (float*)d_out;

    zero_kernel<<<(NN * HID + 255) / 256, 256>>>();
    degree_kernel<<<(NE + 255) / 256, 256>>>(src, dst);
    norm_kernel<<<(NN + 255) / 256, 256>>>();
    gemm1_kernel<<<dim3((NN + RPB - 1) / RPB, NSPLIT), TPB>>>(features, W1);
    scatter1_kernel<<<(NE * 4 + 255) / 256, 256>>>(src, dst);
    act_gemm2_kernel<<<(NN + 255) / 256, 256>>>(b1, W2);
    scatter2_kernel<<<(NE * 2 + 255) / 256, 256>>>(src, dst);
    final_kernel<<<(NN * NL + 255) / 256, 256>>>(b2, out);
}

// round 4
// speedup vs baseline: 2.4910x; 1.1738x over previous
#include <cuda_runtime.h>

#define NN    10000
#define NE    320000
#define HID   16
#define NL    7
#define KTOT  10000

// gemm1 tiling
#define TPB     128          // threads = rows per block
#define RPB     128
#define KS      32           // k per inner step
#define SMAX    12           // steps per chunk
#define KC      (KS * SMAX)  // 384 k per chunk
#define NSPLIT  27           // ceil(10000/384)
#define APITCH  36           // floats per staged row (odd 16B-unit stride)

// -------- scratch (no allocations allowed) --------
__device__ float g_deg_out[NN];
__device__ float g_deg_in[NN];
__device__ float g_norm_src[NN];
__device__ float g_norm_dst[NN];
__device__ float g_h[NN * HID];
__device__ float g_agg1[NN * HID];
__device__ float g_h2[NN * 8];
__device__ float g_agg2[NN * 8];
__device__ int   g_is64;

// -------- zero accumulators --------
__global__ void zero_kernel() {
    int i = blockIdx.x * blockDim.x + threadIdx.x;
    if (i < NN) { g_deg_out[i] = 0.f; g_deg_in[i] = 0.f; }
    if (i < NN * HID) { g_h[i] = 0.f; g_agg1[i] = 0.f; }
}

// -------- degrees (+ inline int64/int32 detection) --------
__global__ void degree_kernel(const int* __restrict__ src, const int* __restrict__ dst) {
    int is64 = ((src[1] | src[3] | src[5] | src[7] |
                 dst[1] | dst[3] | dst[5] | dst[7]) == 0) ? 1 : 0;
    int e = blockIdx.x * blockDim.x + threadIdx.x;
    if (e == 0) g_is64 = is64;
    if (e >= NE) return;
    int s = is64 ? src[2 * e] : src[e];
    int d = is64 ? dst[2 * e] : dst[e];
    atomicAdd(&g_deg_out[s], 1.f);
    atomicAdd(&g_deg_in[d], 1.f);
}

// -------- rsqrt norms --------
__global__ void norm_kernel() {
    int i = blockIdx.x * blockDim.x + threadIdx.x;
    if (i >= NN) return;
    g_norm_src[i] = rsqrtf(fmaxf(g_deg_out[i], 1.f));
    g_norm_dst[i] = rsqrtf(fmaxf(g_deg_in[i], 1.f));
}

// -------- layer1 GEMM: cp.async double-buffered, broadcast-W compute --------
__global__ __launch_bounds__(TPB, 5) void gemm1_kernel(const float* __restrict__ A,
                                                       const float* __restrict__ W1) {
    __shared__ float As[2][RPB * APITCH];   // 2 x 18432 B
    __shared__ float Ww[2][KS * HID];       // 2 x 2048 B

    const int t  = threadIdx.x;
    const int r0 = blockIdx.x * RPB;
    const int k0 = blockIdx.y * KC;
    const int S  = min(SMAX, (KTOT - k0 + KS - 1) >> 5);

    const int srow = t >> 3;        // staging: fixed seg per thread, 8 rows
    const int sseg = t & 7;
    const int kwi  = t >> 2;        // W staging
    const int kwu  = t & 3;

    unsigned long long acc[8];
#pragma unroll
    for (int j = 0; j < 8; j++) acc[j] = 0ull;

    auto prefetch = [&](int s, int b) {
        const int kbase = k0 + s * KS;
        const bool kok = (kbase + sseg * 4) < KTOT;
        unsigned sA = (unsigned)__cvta_generic_to_shared(&As[b][srow * APITCH + sseg * 4]);
#pragma unroll
        for (int i = 0; i < 8; i++) {
            int gr = r0 + srow + 16 * i;
            bool ok = kok && (gr < NN);
            const void* gp = ok ? (const void*)(A + (size_t)gr * KTOT + kbase + sseg * 4)
                                : (const void*)A;
            int n = ok ? 16 : 0;
            asm volatile("cp.async.cg.shared.global [%0], [%1], 16, %2;"
                         :: "r"(sA + i * 16 * APITCH * 4), "l"(gp), "r"(n));
        }
        int gk = kbase + kwi;
        bool ok = gk < KTOT;
        const void* gp = ok ? (const void*)(W1 + (size_t)gk * HID + kwu * 4)
                            : (const void*)W1;
        int n = ok ? 16 : 0;
        unsigned sW = (unsigned)__cvta_generic_to_shared(&Ww[b][kwi * HID + kwu * 4]);
        asm volatile("cp.async.cg.shared.global [%0], [%1], 16, %2;"
                     :: "r"(sW), "l"(gp), "r"(n));
        asm volatile("cp.async.commit_group;");
    };

    prefetch(0, 0);

    for (int s = 0; s < S; s++) {
        __syncthreads();                     // compute(s-1) done -> safe to overwrite other buf
        if (s + 1 < S) {
            prefetch(s + 1, (s + 1) & 1);
            asm volatile("cp.async.wait_group 1;");
        } else {
            asm volatile("cp.async.wait_group 0;");
        }
        __syncthreads();                     // buffer s visible to all

        const float* as = &As[s & 1][t * APITCH];
        const float* wp = Ww[s & 1];
#pragma unroll
        for (int kq = 0; kq < KS / 4; kq++) {
            float4 a = *reinterpret_cast<const float4*>(as + kq * 4);
#pragma unroll
            for (int kk = 0; kk < 4; kk++) {
                float av = kk == 0 ? a.x : kk == 1 ? a.y : kk == 2 ? a.z : a.w;
                unsigned long long d;
                asm("mov.b64 %0, {%1, %1};" : "=l"(d) : "r"(__float_as_uint(av)));
                const ulonglong2* wr =
                    reinterpret_cast<const ulonglong2*>(wp + (kq * 4 + kk) * HID);
                ulonglong2 wa = wr[0], wb = wr[1], wc = wr[2], wd = wr[3];
                unsigned long long w[8] = {wa.x, wa.y, wb.x, wb.y, wc.x, wc.y, wd.x, wd.y};
#pragma unroll
                for (int j = 0; j < 8; j++) {
                    asm("fma.rn.f32x2 %0, %1, %2, %0;" : "+l"(acc[j]) : "l"(d), "l"(w[j]));
                }
            }
        }
    }

    const int r = r0 + t;
    if (r < NN) {
        float ns = g_norm_src[r];
#pragma unroll
        for (int j = 0; j < 8; j++) {
            float2 p = *reinterpret_cast<float2*>(&acc[j]);
            atomicAdd(&g_h[r * HID + 2 * j],     p.x * ns);
            atomicAdd(&g_h[r * HID + 2 * j + 1], p.y * ns);
        }
    }
}

// -------- edge scatter 1 (float4-vectorized): agg1[dst] += h[src] --------
__global__ void scatter1_kernel(const int* __restrict__ src, const int* __restrict__ dst) {
    int idx = blockIdx.x * blockDim.x + threadIdx.x;
    if (idx >= NE * 4) return;
    int e = idx >> 2, q = idx & 3;
    int is64 = g_is64;
    int s = is64 ? src[2 * e] : src[e];
    int d = is64 ? dst[2 * e] : dst[e];
    float4 v = *reinterpret_cast<const float4*>(&g_h[s * HID + q * 4]);
    float* o = &g_agg1[d * HID + q * 4];
    atomicAdd(o + 0, v.x); atomicAdd(o + 1, v.y);
    atomicAdd(o + 2, v.z); atomicAdd(o + 3, v.w);
}

// -------- relu + norm + layer2 GEMM (16x7), also zeroes agg2 --------
__global__ void act_gemm2_kernel(const float* __restrict__ b1, const float* __restrict__ W2) {
    __shared__ float W2s[HID * NL];
    __shared__ float b1s[HID];
    int t = threadIdx.x;
    if (t < HID * NL) W2s[t] = W2[t];
    if (t < HID) b1s[t] = b1[t];
    __syncthreads();
    int i = blockIdx.x * blockDim.x + t;
    if (i >= NN) return;
    *reinterpret_cast<float4*>(&g_agg2[i * 8])     = make_float4(0.f, 0.f, 0.f, 0.f);
    *reinterpret_cast<float4*>(&g_agg2[i * 8 + 4]) = make_float4(0.f, 0.f, 0.f, 0.f);

    float nd = g_norm_dst[i], ns = g_norm_src[i];
    float o[8];
#pragma unroll
    for (int l = 0; l < 8; l++) o[l] = 0.f;
    const float4* ag = (const float4*)(g_agg1 + i * HID);
#pragma unroll
    for (int q = 0; q < 4; q++) {
        float4 v = ag[q];
        float hv[4] = {v.x, v.y, v.z, v.w};
#pragma unroll
        for (int u = 0; u < 4; u++) {
            int j = q * 4 + u;
            float h1 = fmaxf(hv[u] * nd + b1s[j], 0.f) * ns;
#pragma unroll
            for (int l = 0; l < NL; l++) o[l] += h1 * W2s[j * NL + l];
        }
    }
    *reinterpret_cast<float4*>(&g_h2[i * 8])     = make_float4(o[0], o[1], o[2], o[3]);
    *reinterpret_cast<float4*>(&g_h2[i * 8 + 4]) = make_float4(o[4], o[5], o[6], 0.f);
}

// -------- edge scatter 2 (float4-vectorized, padded to 8 cols) --------
__global__ void scatter2_kernel(const int* __restrict__ src, const int* __restrict__ dst) {
    int idx = blockIdx.x * blockDim.x + threadIdx.x;
    if (idx >= NE * 2) return;
    int e = idx >> 1, q = idx & 1;
    int is64 = g_is64;
    int s = is64 ? src[2 * e] : src[e];
    int d = is64 ? dst[2 * e] : dst[e];
    float4 v = *reinterpret_cast<const float4*>(&g_h2[s * 8 + q * 4]);
    float* o = &g_agg2[d * 8 + q * 4];
    atomicAdd(o + 0, v.x); atomicAdd(o + 1, v.y);
    atomicAdd(o + 2, v.z); atomicAdd(o + 3, v.w);
}

// -------- epilogue: out = agg2 * norm_dst + b2 --------
__global__ void final_kernel(const float* __restrict__ b2, float* __restrict__ out) {
    int idx = blockIdx.x * blockDim.x + threadIdx.x;
    if (idx >= NN * NL) return;
    int i = idx / NL, l = idx - i * NL;
    out[idx] = g_agg2[i * 8 + l] * g_norm_dst[i] + __ldg(&b2[l]);
}

extern "C" void kernel_launch(void* const* d_in, const int* in_sizes, int n_in,
                              void* d_out, int out_size) {
    const float* features = (const float*)d_in[0];
    const int*   src      = (const int*)d_in[1];   // int32 or int64 (runtime-detected)
    const int*   dst      = (const int*)d_in[2];
    const float* W1       = (const float*)d_in[3];
    const float* b1       = (const float*)d_in[4];
    const float* W2       = (const float*)d_in[5];
    const float* b2       = (const float*)d_in[6];
    float* out = (float*)d_out;

    zero_kernel<<<(NN * HID + 255) / 256, 256>>>();
    degree_kernel<<<(NE + 255) / 256, 256>>>(src, dst);
    norm_kernel<<<(NN + 255) / 256, 256>>>();
    gemm1_kernel<<<dim3((NN + RPB - 1) / RPB, NSPLIT), TPB>>>(features, W1);
    scatter1_kernel<<<(NE * 4 + 255) / 256, 256>>>(src, dst);
    act_gemm2_kernel<<<(NN + 255) / 256, 256>>>(b1, W2);
    scatter2_kernel<<<(NE * 2 + 255) / 256, 256>>>(src, dst);
    final_kernel<<<(NN * NL + 255) / 256, 256>>>(b2, out);
}